// round 3
// baseline (speedup 1.0000x reference)
#include <cuda_runtime.h>
#include <cstdint>

// ---------------- problem constants ----------------
#define B      128
#define D      768
#define POOL   100
#define LG     6
#define LE     6
#define GLEN   5
#define ELEN   20
#define H      12
#define HD     64
#define TOPK   5

// g_out: [LG,2,B,H,GLEN,HD]  floats
#define G_FLOATS   (LG*2*B*H*GLEN*HD)          // 5,898,240
#define G_VEC4     (G_FLOATS/4)                // 1,474,560
// e_out: [LE,2,B,H,TOPK*ELEN,HD] floats
#define E_FLOATS   (LE*2*B*H*(TOPK*ELEN)*HD)   // 117,964,800
#define E_VEC4     (E_FLOATS/4)                // 29,491,200
#define TOTAL_VEC4 (G_VEC4 + E_VEC4)

// 4 float4 (64B) per thread-group
#define G_GROUPS     (G_VEC4/4)                 // 368,640
#define TOTAL_GROUPS (TOTAL_VEC4/4)             // 7,741,440

// scratch for selected indices (no cudaMalloc allowed)
__device__ int d_idx[B * TOPK];

// ---------------------------------------------------------------------------
// Kernel 1: cosine-sim + top-5 selection.
// One block per query row: 512 threads = 16 warps.
//  - qn is skipped: it is a positive per-row constant, so ranking by
//    dot/kn is identical (including ties) to dot/(qn*kn).
//  - query row preloaded into registers per warp (6 float4/lane), reused.
//  - warp-parallel argmax top-5 with lowest-index tie-break (matches
//    jax.lax.top_k ordering).
// ---------------------------------------------------------------------------
__global__ __launch_bounds__(512) void select_topk_kernel(
        const float4* __restrict__ query4,
        const float4* __restrict__ keys4) {
    const int b    = blockIdx.x;
    const int t    = threadIdx.x;
    const int warp = t >> 5;
    const int lane = t & 31;

    __shared__ float sims[POOL];

    // preload query row: 192 float4, lane-strided, 6 per lane
    const float4* qr = query4 + (size_t)b * (D / 4);
    float4 fq[6];
    #pragma unroll
    for (int j = 0; j < 6; j++) fq[j] = __ldg(&qr[lane + 32 * j]);

    // each warp: pool entries p = warp, warp+16, ...  (~6-7 each)
    for (int p = warp; p < POOL; p += 16) {
        const float4* kr = keys4 + (size_t)p * (D / 4);
        float dot = 0.f, kk = 0.f;
        #pragma unroll
        for (int j = 0; j < 6; j++) {
            float4 kv = __ldg(&kr[lane + 32 * j]);
            dot = fmaf(fq[j].x, kv.x, dot);
            dot = fmaf(fq[j].y, kv.y, dot);
            dot = fmaf(fq[j].z, kv.z, dot);
            dot = fmaf(fq[j].w, kv.w, dot);
            kk  = fmaf(kv.x, kv.x, kk);
            kk  = fmaf(kv.y, kv.y, kk);
            kk  = fmaf(kv.z, kv.z, kk);
            kk  = fmaf(kv.w, kv.w, kk);
        }
        #pragma unroll
        for (int o = 16; o > 0; o >>= 1) {
            dot += __shfl_xor_sync(0xFFFFFFFFu, dot, o);
            kk  += __shfl_xor_sync(0xFFFFFFFFu, kk,  o);
        }
        if (lane == 0) {
            float kn = fmaxf(sqrtf(kk), 1e-12f);
            sims[p] = dot / kn;
        }
    }
    __syncthreads();

    // warp 0: parallel top-5 argmax, tie-break = lowest index
    if (warp == 0) {
        #pragma unroll
        for (int k = 0; k < TOPK; k++) {
            float best = -3.0e38f;
            int   bi   = POOL;
            #pragma unroll
            for (int j = 0; j < 4; j++) {          // p = lane, lane+32, +64, +96
                int p = lane + 32 * j;
                if (p < POOL) {
                    float v = sims[p];
                    if (v > best) { best = v; bi = p; }   // increasing p scan -> lowest idx kept
                }
            }
            #pragma unroll
            for (int o = 16; o > 0; o >>= 1) {
                float ov = __shfl_xor_sync(0xFFFFFFFFu, best, o);
                int   oi = __shfl_xor_sync(0xFFFFFFFFu, bi,   o);
                if (ov > best || (ov == best && oi < bi)) { best = ov; bi = oi; }
            }
            if (lane == 0) {
                d_idx[b * TOPK + k] = bi;
                sims[bi] = -3.0e38f;
            }
            __syncwarp();
        }
    }
}

// ---------------------------------------------------------------------------
// Kernel 2: fused output writer. Each thread handles a 64-byte quarter-row
// (4 consecutive float4): one coordinate computation, 4 independent loads,
// 4 coalesced streaming stores.
//   g region: out[l,d,b,h,g,:] = g_prompt[l,d,g,h,:]
//   e region: out[l,d,b,h,m,:] = pool[idx[b][m/ELEN], l, d, m%ELEN, h, :]
// ---------------------------------------------------------------------------
__global__ __launch_bounds__(256) void write_out_kernel(
        const float4* __restrict__ g4,
        const float4* __restrict__ pool4,
        float4* __restrict__ out4) {
    long long gid = (long long)blockIdx.x * blockDim.x + threadIdx.x;
    if (gid >= (long long)TOTAL_GROUPS) return;

    const float4* src;
    if (gid < (long long)G_GROUPS) {
        int v  = (int)gid;
        int q  = v & 3;   v >>= 2;      // which 64B quarter of the 256B row
        int gl = v % GLEN; v /= GLEN;
        int h  = v % H;    v /= H;
        v >>= 7;                         // drop b (128)
        int ld = v;                      // l*2+d in [0,12)
        // src float4 layout: [LG*2, GLEN, H, 16]
        src = &g4[(((ld * GLEN + gl) * H + h) << 4) + (q << 2)];
    } else {
        long long v = gid - G_GROUPS;
        int q  = (int)(v & 3); v >>= 2;
        int m  = (int)(v % (TOPK * ELEN)); v /= (TOPK * ELEN);  // 100
        int h  = (int)(v % H); v /= H;
        int b  = (int)(v & 127); v >>= 7;
        int ld = (int)v;                 // l*2+d in [0,12)
        int k  = m / ELEN;
        int e  = m - k * ELEN;
        int p  = d_idx[b * TOPK + k];
        // pool float4 layout: [POOL, LE*2(=12), ELEN, H, 16]
        src = &pool4[((((((long long)p * 12 + ld) * ELEN + e) * H + h)) << 4) + (q << 2)];
    }

    float4 v0 = __ldg(src + 0);
    float4 v1 = __ldg(src + 1);
    float4 v2 = __ldg(src + 2);
    float4 v3 = __ldg(src + 3);

    float4* dst = out4 + gid * 4;
    __stcs(dst + 0, v0);
    __stcs(dst + 1, v1);
    __stcs(dst + 2, v2);
    __stcs(dst + 3, v3);
}

// ---------------------------------------------------------------------------
extern "C" void kernel_launch(void* const* d_in, const int* in_sizes, int n_in,
                              void* d_out, int out_size) {
    const float* query = (const float*)d_in[0];
    const float* gprm  = (const float*)d_in[1];
    const float* pool  = (const float*)d_in[2];
    const float* keys  = (const float*)d_in[3];
    float* out = (float*)d_out;

    // 1. top-k selection
    select_topk_kernel<<<B, 512>>>((const float4*)query, (const float4*)keys);

    // 2. fused g + e writer (depends on d_idx; same stream => ordered)
    {
        const int threads = 256;
        int blocks = (int)((TOTAL_GROUPS + threads - 1) / threads);   // 30,240
        write_out_kernel<<<blocks, threads>>>((const float4*)gprm,
                                              (const float4*)pool,
                                              (float4*)out);
    }
}

// round 4
// speedup vs baseline: 1.6581x; 1.6581x over previous
#include <cuda_runtime.h>
#include <cstdint>

// ---------------- problem constants ----------------
#define B      128
#define D      768
#define POOL   100
#define LG     6
#define LE     6
#define GLEN   5
#define ELEN   20
#define H      12
#define HD     64
#define TOPK   5

// Output rows: one row = HD floats = 16 float4 = 256 bytes.
// g_out: [LG,2,B,H,GLEN,HD] -> G_ROWS = 6*2*128*12*5 = 92,160
#define G_ROWS     (LG*2*B*H*GLEN)              // 92,160
// e_out: [LE,2,B,H,TOPK*ELEN,HD] -> E_ROWS = 6*2*128*12*100 = 1,843,200
#define E_ROWS     (LE*2*B*H*(TOPK*ELEN))       // 1,843,200
#define TOTAL_ROWS (G_ROWS + E_ROWS)            // 1,935,360
// Each thread handles one (row, half-slot): 2 float4 at c4h and c4h+8.
#define TOTAL_PAIRS (TOTAL_ROWS * 8)            // 15,482,880

// scratch for selected indices (no cudaMalloc allowed)
__device__ int d_idx[B * TOPK];

// ---------------------------------------------------------------------------
// Kernel 1: cosine-sim + top-5 selection (proven ~4-7us incl. overhead).
// One block per query row: 512 threads = 16 warps; warp-per-dot-product with
// float4 coalesced loads; qn dropped (positive per-row constant, ranking
// invariant); warp-parallel argmax with lowest-index tie-break.
// ---------------------------------------------------------------------------
__global__ __launch_bounds__(512) void select_topk_kernel(
        const float4* __restrict__ query4,
        const float4* __restrict__ keys4) {
    const int b    = blockIdx.x;
    const int t    = threadIdx.x;
    const int warp = t >> 5;
    const int lane = t & 31;

    __shared__ float sims[POOL];

    const float4* qr = query4 + (size_t)b * (D / 4);
    float4 fq[6];
    #pragma unroll
    for (int j = 0; j < 6; j++) fq[j] = __ldg(&qr[lane + 32 * j]);

    for (int p = warp; p < POOL; p += 16) {
        const float4* kr = keys4 + (size_t)p * (D / 4);
        float dot = 0.f, kk = 0.f;
        #pragma unroll
        for (int j = 0; j < 6; j++) {
            float4 kv = __ldg(&kr[lane + 32 * j]);
            dot = fmaf(fq[j].x, kv.x, dot);
            dot = fmaf(fq[j].y, kv.y, dot);
            dot = fmaf(fq[j].z, kv.z, dot);
            dot = fmaf(fq[j].w, kv.w, dot);
            kk  = fmaf(kv.x, kv.x, kk);
            kk  = fmaf(kv.y, kv.y, kk);
            kk  = fmaf(kv.z, kv.z, kk);
            kk  = fmaf(kv.w, kv.w, kk);
        }
        #pragma unroll
        for (int o = 16; o > 0; o >>= 1) {
            dot += __shfl_xor_sync(0xFFFFFFFFu, dot, o);
            kk  += __shfl_xor_sync(0xFFFFFFFFu, kk,  o);
        }
        if (lane == 0) {
            float kn = fmaxf(sqrtf(kk), 1e-12f);
            sims[p] = dot / kn;
        }
    }
    __syncthreads();

    if (warp == 0) {
        #pragma unroll
        for (int k = 0; k < TOPK; k++) {
            float best = -3.0e38f;
            int   bi   = POOL;
            #pragma unroll
            for (int j = 0; j < 4; j++) {
                int p = lane + 32 * j;
                if (p < POOL) {
                    float v = sims[p];
                    if (v > best) { best = v; bi = p; }
                }
            }
            #pragma unroll
            for (int o = 16; o > 0; o >>= 1) {
                float ov = __shfl_xor_sync(0xFFFFFFFFu, best, o);
                int   oi = __shfl_xor_sync(0xFFFFFFFFu, bi,   o);
                if (ov > best || (ov == best && oi < bi)) { best = ov; bi = oi; }
            }
            if (lane == 0) {
                d_idx[b * TOPK + k] = bi;
                sims[bi] = -3.0e38f;
            }
            __syncwarp();
        }
    }
}

// ---------------------------------------------------------------------------
// Kernel 2: fused output writer.
// One thread = one (row, half-slot): 2 float4 at columns c4h and c4h+8 of a
// 256B row. Index math computed ONCE per thread serves 2 loads + 2 stores.
// Warp access pattern: 4 consecutive 256B rows x bytes [c4h*16 .. +127]
//  => every LDG/STG covers exactly 4 full 128B lines (perfect coalescing).
//   g region: out[l,d,b,h,gl,:] = g_prompt[l,d,gl,h,:]
//   e region: out[l,d,b,h,m,:]  = pool[idx[b][m/ELEN], l, d, m%ELEN, h, :]
// ---------------------------------------------------------------------------
__global__ __launch_bounds__(256) void write_out_kernel(
        const float4* __restrict__ g4,
        const float4* __restrict__ pool4,
        float4* __restrict__ out4) {
    int gid = blockIdx.x * blockDim.x + threadIdx.x;
    if (gid >= TOTAL_PAIRS) return;

    const int c4h = gid & 7;       // half-slot 0..7
    const int row = gid >> 3;      // output row (256B granule)

    const float4* src;
    if (row < G_ROWS) {
        // row = ((ld*B + b)*H + h)*GLEN + gl
        int v  = row;
        int gl = v % GLEN; v /= GLEN;
        int h  = v % H;    v /= H;
        v >>= 7;                              // drop b
        int ld = v;                           // 0..11
        src = &g4[(((ld * GLEN + gl) * H + h) << 4) + c4h];
    } else {
        // row_e = ((ld*B + b)*H + h)*100 + m
        int v  = row - G_ROWS;
        int m  = v % (TOPK * ELEN); v /= (TOPK * ELEN);
        int h  = v % H;             v /= H;
        int b  = v & 127;           v >>= 7;
        int ld = v;                           // 0..11
        int k  = m / ELEN;
        int e  = m - k * ELEN;
        int p  = __ldg(&d_idx[b * TOPK + k]);
        src = &pool4[((((p * 12 + ld) * ELEN + e) * H + h) << 4) + c4h];
    }

    float4 v0 = __ldg(src);
    float4 v1 = __ldg(src + 8);

    float4* dst = out4 + ((long long)row << 4) + c4h;
    __stcs(dst,     v0);
    __stcs(dst + 8, v1);
}

// ---------------------------------------------------------------------------
extern "C" void kernel_launch(void* const* d_in, const int* in_sizes, int n_in,
                              void* d_out, int out_size) {
    const float* query = (const float*)d_in[0];
    const float* gprm  = (const float*)d_in[1];
    const float* pool  = (const float*)d_in[2];
    const float* keys  = (const float*)d_in[3];
    float* out = (float*)d_out;

    // 1. top-k selection
    select_topk_kernel<<<B, 512>>>((const float4*)query, (const float4*)keys);

    // 2. fused g + e writer (depends on d_idx; same stream => ordered)
    {
        const int threads = 256;
        int blocks = (TOTAL_PAIRS + threads - 1) / threads;   // 60,480
        write_out_kernel<<<blocks, threads>>>((const float4*)gprm,
                                              (const float4*)pool,
                                              (float4*)out);
    }
}